// round 4
// baseline (speedup 1.0000x reference)
#include <cuda_runtime.h>
#include <cstddef>

#define BB 4
#define LL 2048
#define HH 8
#define DD 64
#define SK 40
#define NT 40
#define BHN 32
#define NSPLIT 16
#define CHUNK 128
#define SCALE 0.125f

#define CK 384          // strip rows
#define NKC 6
#define LQ 4            // l-quarters
#define LPB 512         // l's per block

// ---------------- scratch ----------------
__device__ int   g_is64;
__device__ int   g_idx32[LL * SK];
__device__ float g_M[BHN * LL];
__device__ int   g_top[BHN * NT];
__device__ float g_pm[BHN * NSPLIT * NT];
__device__ float g_pl[BHN * NSPLIT * NT];
__device__ float g_po[BHN * NSPLIT * NT * DD];

// ---------------- packed f32x2 helpers ----------------
__device__ __forceinline__ unsigned long long pk2(float x, float y) {
    unsigned long long r;
    asm("mov.b64 %0, {%1, %2};" : "=l"(r) : "f"(x), "f"(y));
    return r;
}
__device__ __forceinline__ void upk2(unsigned long long v, float& x, float& y) {
    asm("mov.b64 {%0, %1}, %2;" : "=f"(x), "=f"(y) : "l"(v));
}
__device__ __forceinline__ unsigned long long ffma2(unsigned long long a,
                                                    unsigned long long b,
                                                    unsigned long long c) {
    unsigned long long d;
    asm("fma.rn.f32x2 %0, %1, %2, %3;" : "=l"(d) : "l"(a), "l"(b), "l"(c));
    return d;
}
__device__ __forceinline__ unsigned long long fmul2(unsigned long long a,
                                                    unsigned long long b) {
    unsigned long long d;
    asm("mul.rn.f32x2 %0, %1, %2;" : "=l"(d) : "l"(a), "l"(b));
    return d;
}

// ---------------- detect index dtype ----------------
__global__ void detect_idx_kernel(const long long* __restrict__ idx64) {
    int ok = 1;
    for (int i = threadIdx.x; i < 512; i += 32) {
        long long v = idx64[i];
        if (v < 0 || v >= LL) ok = 0;
    }
    unsigned m = __ballot_sync(0xffffffffu, ok);
    if (threadIdx.x == 0) g_is64 = (m == 0xffffffffu) ? 1 : 0;
}

// ---------------- convert indices to int32 ----------------
__global__ void idx_convert_kernel(const void* __restrict__ idxbuf) {
    int e = blockIdx.x * 256 + threadIdx.x;   // grid covers LL*SK exactly
    g_idx32[e] = g_is64 ? (int)((const long long*)idxbuf)[e]
                        : ((const int*)idxbuf)[e];
}

// ---------------- sample_m v5: strip-staged smem gather ----------------
// block = (bh, l-quarter). Loops 6 K-strips; per l, ballot in-strip samples,
// process 4 hits/round via 4 groups x 8 lanes; (max,sum) acc in smem.
__global__ void sample_m_kernel(const float* __restrict__ Q,
                                const float* __restrict__ K) {
    extern __shared__ float smem[];
    float* Ks    = smem;                 // CK*64 = 24576 floats
    float* accMx = Ks + CK * DD;         // 512
    float* accSm = accMx + LPB;          // 512

    int bh = blockIdx.x / LQ, lq = blockIdx.x % LQ;
    int b = bh >> 3, h = bh & 7;
    int t = threadIdx.x;
    int w = t >> 5, lane = t & 31;
    int g = lane >> 3, li = lane & 7;

    for (int i = t; i < LPB; i += 256) { accMx[i] = -3e38f; accSm[i] = 0.f; }

    for (int kc = 0; kc < NKC; kc++) {
        __syncthreads();   // prior strip reads done before restage
        int lo = kc * CK;
        int rows = min(CK, LL - lo);
        for (int i = t; i < rows * 16; i += 256) {
            int rr = i >> 4, c4 = i & 15;
            ((float4*)Ks)[(rr << 4) + c4] =
                ((const float4*)(K + (((size_t)(b * LL + lo + rr) * HH + h) << 6)))[c4];
        }
        __syncthreads();

        int lbase = lq * LPB + w * 64;
        for (int ll = 0; ll < 64; ll++) {
            int l = lbase + ll;
            const int* ip = g_idx32 + l * SK;
            int i0 = ip[lane];
            int i1 = (lane < 8) ? ip[32 + lane] : 0x7fffffff;
            unsigned mA = __ballot_sync(0xffffffffu, (unsigned)(i0 - lo) < (unsigned)rows);
            unsigned mB = __ballot_sync(0xffffffffu,
                                        (lane < 8) && ((unsigned)(i1 - lo) < (unsigned)rows));
            int pcA = __popc(mA);
            int nh = pcA + __popc(mB);
            if (nh == 0) continue;

            const float* qb = Q + (((size_t)(b * LL + l) * HH + h) << 6) + (li << 3);
            float4 qa = ((const float4*)qb)[0];
            float4 qz = ((const float4*)qb)[1];

            float mx = -3e38f, sm = 0.f;
            int nr = (nh + 3) >> 2;
            for (int r = 0; r < nr; r++) {
                int hh = r * 4 + g;
                int act = (hh < nh);
                unsigned bpos = 0;
                if (act) {
                    bpos = (hh < pcA) ? __fns(mA, 0, hh + 1)
                                      : 32u + __fns(mB, 0, hh - pcA + 1);
                }
                int jA = __shfl_sync(0xffffffffu, i0, bpos & 31);
                int jB = __shfl_sync(0xffffffffu, i1, bpos & 7);
                int jl = ((bpos < 32) ? jA : jB) - lo;
                if (!act) jl = 0;
                const float4* kp = (const float4*)(Ks + (jl << 6) + (li << 3));
                float4 k0 = kp[0];
                float4 k1 = kp[1];
                float p = qa.x * k0.x;
                p = fmaf(qa.y, k0.y, p);
                p = fmaf(qa.z, k0.z, p);
                p = fmaf(qa.w, k0.w, p);
                p = fmaf(qz.x, k1.x, p);
                p = fmaf(qz.y, k1.y, p);
                p = fmaf(qz.z, k1.z, p);
                p = fmaf(qz.w, k1.w, p);
                p += __shfl_xor_sync(0xffffffffu, p, 1);
                p += __shfl_xor_sync(0xffffffffu, p, 2);
                p += __shfl_xor_sync(0xffffffffu, p, 4);
                if (act) { mx = fmaxf(mx, p); sm += p; }
            }
            // cross-group combine
            mx = fmaxf(mx, __shfl_xor_sync(0xffffffffu, mx, 8));
            mx = fmaxf(mx, __shfl_xor_sync(0xffffffffu, mx, 16));
            sm += __shfl_xor_sync(0xffffffffu, sm, 8);
            sm += __shfl_xor_sync(0xffffffffu, sm, 16);
            if (lane == 0) {
                int a = w * 64 + ll;
                accMx[a] = fmaxf(accMx[a], mx);
                accSm[a] += sm;
            }
        }
    }
    __syncthreads();
    for (int i = t; i < LPB; i += 256)
        g_M[bh * LL + lq * LPB + i] = accMx[i] - accSm[i] * (1.0f / (float)LL);
}

// ---------------- top-40 per bh (unchanged, proven) ----------------
__global__ void topk_kernel() {
    __shared__ float sM[LL];
    int bh = blockIdx.x, lane = threadIdx.x;
    for (int i = lane; i < LL; i += 32) sM[i] = g_M[bh * LL + i];
    __syncwarp();

    float bv = -3e38f; int bi = lane * 64;
    for (int i = 0; i < 64; i++) {
        float x = sM[lane * 64 + i];
        if (x > bv) { bv = x; bi = lane * 64 + i; }
    }
    for (int it = 0; it < NT; it++) {
        unsigned uv = __float_as_uint(bv);
        uv ^= (uv >> 31) ? 0xffffffffu : 0x80000000u;
        unsigned long long key = ((unsigned long long)uv << 32) | (unsigned)(LL - 1 - bi);
#pragma unroll
        for (int o = 16; o; o >>= 1) {
            unsigned long long ok = __shfl_xor_sync(0xffffffffu, key, o);
            if (ok > key) key = ok;
        }
        int wi = LL - 1 - (int)(key & 0xffffffffu);
        if (lane == 0) { g_top[bh * NT + it] = wi; sM[wi] = -3e38f; }
        __syncwarp();

        int seg = wi >> 6;
        float x0 = sM[(seg << 6) + lane];
        float x1 = sM[(seg << 6) + 32 + lane];
        float rv; int ri;
        if (x0 >= x1) { rv = x0; ri = (seg << 6) + lane; }
        else          { rv = x1; ri = (seg << 6) + 32 + lane; }
        unsigned ru = __float_as_uint(rv);
        ru ^= (ru >> 31) ? 0xffffffffu : 0x80000000u;
        unsigned long long rkey = ((unsigned long long)ru << 32) | (unsigned)(LL - 1 - ri);
#pragma unroll
        for (int o = 16; o; o >>= 1) {
            unsigned long long ok = __shfl_xor_sync(0xffffffffu, rkey, o);
            if (ok > rkey) rkey = ok;
        }
        if (lane == seg) {
            unsigned nu = (unsigned)(rkey >> 32);
            nu = (nu & 0x80000000u) ? (nu ^ 0x80000000u) : ~nu;
            bv = __uint_as_float(nu);
            bi = LL - 1 - (int)(rkey & 0xffffffffu);
        }
        __syncwarp();
    }
}

// ---------------- split-K attention v2: no Vs stage, f32x2 math ----------------
__global__ void attn_kernel(const float* __restrict__ Q,
                            const float* __restrict__ K,
                            const float* __restrict__ V) {
    extern __shared__ float smem[];
    int bh = blockIdx.x / NSPLIT, split = blockIdx.x % NSPLIT;
    int b = bh >> 3, h = bh & 7;
    int t = threadIdx.x;

    float* Qs = smem;                  // 2560
    float* Kt = Qs + NT * DD;          // 8448
    float* Ss = Kt + 64 * 132;         // 5120  (total 63 KB)

    for (int i = t; i < NT * DD; i += 256) {
        int u = i >> 6, d = i & 63;
        int ql = g_top[bh * NT + u];
        Qs[i] = Q[(((size_t)(b * LL + ql) * HH + h) << 6) + d];
    }
    int key0 = split * CHUNK;
    for (int i = t; i < CHUNK * DD; i += 256) {
        int j = i >> 6, d = i & 63;
        Kt[d * 132 + j] = K[(((size_t)(b * LL + key0 + j) * HH + h) << 6) + d];
    }
    __syncthreads();

    // ---- phase 1: scores (packed f32x2) ----
    {
        int ublk = t >> 5;
        int jg   = t & 31;
        unsigned long long a01[5], a23[5];
#pragma unroll
        for (int k = 0; k < 5; k++) { a01[k] = 0ull; a23[k] = 0ull; }
        const ulonglong2* Kt2 = (const ulonglong2*)Kt;
#pragma unroll 8
        for (int d = 0; d < 64; d++) {
            ulonglong2 kv = Kt2[d * 33 + jg];
#pragma unroll
            for (int k = 0; k < 5; k++) {
                float qv = Qs[(ublk * 5 + k) * 64 + d];
                unsigned long long qq = pk2(qv, qv);
                a01[k] = ffma2(qq, kv.x, a01[k]);
                a23[k] = ffma2(qq, kv.y, a23[k]);
            }
        }
        unsigned long long sc = pk2(SCALE, SCALE);
#pragma unroll
        for (int k = 0; k < 5; k++) {
            int u = ublk * 5 + k;
            ulonglong2 sv;
            sv.x = fmul2(a01[k], sc);
            sv.y = fmul2(a23[k], sc);
            *(ulonglong2*)(Ss + u * CHUNK + (jg << 2)) = sv;
        }
    }
    __syncthreads();

    // ---- phase 1.5: partial softmax ----
    {
        int w = t >> 5, lane = t & 31;
        for (int r = w * 5; r < w * 5 + 5; r++) {
            float v0 = Ss[r * CHUNK + lane];
            float v1 = Ss[r * CHUNK + lane + 32];
            float v2 = Ss[r * CHUNK + lane + 64];
            float v3 = Ss[r * CHUNK + lane + 96];
            float m = fmaxf(fmaxf(v0, v1), fmaxf(v2, v3));
#pragma unroll
            for (int o = 16; o; o >>= 1) m = fmaxf(m, __shfl_xor_sync(0xffffffffu, m, o));
            float e0 = __expf(v0 - m), e1 = __expf(v1 - m);
            float e2 = __expf(v2 - m), e3 = __expf(v3 - m);
            Ss[r * CHUNK + lane]      = e0;
            Ss[r * CHUNK + lane + 32] = e1;
            Ss[r * CHUNK + lane + 64] = e2;
            Ss[r * CHUNK + lane + 96] = e3;
            float s = e0 + e1 + e2 + e3;
#pragma unroll
            for (int o = 16; o; o >>= 1) s += __shfl_xor_sync(0xffffffffu, s, o);
            if (lane == 0) {
                g_pm[(bh * NSPLIT + split) * NT + r] = m;
                g_pl[(bh * NSPLIT + split) * NT + r] = s;
            }
        }
    }
    __syncthreads();

    // ---- phase 2: O_partial = P @ V (V from L1-cached global, packed) ----
    {
        int ublk = t >> 5;
        int d4   = t & 15;
        int jh   = (t >> 4) & 1;
        unsigned long long a01[5], a23[5];
#pragma unroll
        for (int k = 0; k < 5; k++) { a01[k] = 0ull; a23[k] = 0ull; }
        int j0 = jh * 64;
#pragma unroll 4
        for (int jj = 0; jj < 64; jj++) {
            int j = j0 + jj;
            ulonglong2 vv = *(const ulonglong2*)
                (V + (((size_t)(b * LL + key0 + j) * HH + h) << 6) + (d4 << 2));
#pragma unroll
            for (int k = 0; k < 5; k++) {
                float p = Ss[(ublk * 5 + k) * CHUNK + j];
                unsigned long long pp = pk2(p, p);
                a01[k] = ffma2(pp, vv.x, a01[k]);
                a23[k] = ffma2(pp, vv.y, a23[k]);
            }
        }
        float* Opart = Kt;   // reuse
#pragma unroll
        for (int k = 0; k < 5; k++) {
            int u = ublk * 5 + k;
            ulonglong2 ov; ov.x = a01[k]; ov.y = a23[k];
            *(ulonglong2*)(Opart + (jh * NT + u) * 64 + (d4 << 2)) = ov;
        }
    }
    __syncthreads();

    for (int i = t; i < NT * DD; i += 256) {
        float v = Kt[i] + Kt[NT * DD + i];
        g_po[(size_t)(bh * NSPLIT + split) * NT * DD + i] = v;
    }
}

// ---------------- combine v2: 256 blocks ----------------
__global__ void combine_kernel(float* __restrict__ out) {
    __shared__ float sw[5 * NSPLIT];
    __shared__ float sl[5];
    int bid = blockIdx.x;
    int bh = bid >> 3, uc = bid & 7;
    int b = bh >> 3, h = bh & 7;
    int t = threadIdx.x;

    if (t < 5) {
        int u = uc * 5 + t;
        float m = -3e38f;
#pragma unroll
        for (int s = 0; s < NSPLIT; s++)
            m = fmaxf(m, g_pm[(bh * NSPLIT + s) * NT + u]);
        float Ls = 0.f;
#pragma unroll
        for (int s = 0; s < NSPLIT; s++) {
            float w = __expf(g_pm[(bh * NSPLIT + s) * NT + u] - m);
            sw[t * NSPLIT + s] = w;
            Ls += g_pl[(bh * NSPLIT + s) * NT + u] * w;
        }
        sl[t] = Ls;
    }
    __syncthreads();
    for (int i = t; i < 5 * DD; i += 256) {
        int uu = i >> 6, d = i & 63;
        int u = uc * 5 + uu;
        float acc = 0.f;
#pragma unroll
        for (int s = 0; s < NSPLIT; s++)
            acc += sw[uu * NSPLIT + s] *
                   g_po[(size_t)(bh * NSPLIT + s) * NT * DD + u * DD + d];
        out[(((size_t)(b * NT + u) * HH + h) << 6) + d] = acc / sl[uu];
    }
}

// ---------------- launcher ----------------
extern "C" void kernel_launch(void* const* d_in, const int* in_sizes, int n_in,
                              void* d_out, int out_size) {
    const float* Q   = (const float*)d_in[0];
    const float* K   = (const float*)d_in[1];
    const float* V   = (const float*)d_in[2];
    const void*  idx = d_in[3];

    detect_idx_kernel<<<1, 32>>>((const long long*)idx);
    idx_convert_kernel<<<(LL * SK) / 256, 256>>>(idx);

    size_t smemS = (size_t)(CK * DD + 2 * LPB) * sizeof(float);   // 102400 B
    cudaFuncSetAttribute(sample_m_kernel, cudaFuncAttributeMaxDynamicSharedMemorySize, (int)smemS);
    sample_m_kernel<<<BHN * LQ, 256, smemS>>>(Q, K);

    topk_kernel<<<BHN, 32>>>();

    size_t smemD = (size_t)(NT * DD + 64 * 132 + NT * CHUNK) * sizeof(float); // 64512 B
    cudaFuncSetAttribute(attn_kernel, cudaFuncAttributeMaxDynamicSharedMemorySize, (int)smemD);
    attn_kernel<<<BHN * NSPLIT, 256, smemD>>>(Q, K, V);

    combine_kernel<<<BHN * 8, 256>>>((float*)d_out);
}

// round 5
// speedup vs baseline: 3.9217x; 3.9217x over previous
#include <cuda_runtime.h>
#include <cstddef>

#define BB 4
#define LL 2048
#define HH 8
#define DD 64
#define SK 40
#define NT 40
#define BHN 32
#define NSPLIT 16
#define CHUNK 128
#define SCALE 0.125f

// ---------------- scratch ----------------
__device__ int   g_is64;
__device__ float g_M[BHN * LL];
__device__ int   g_top[BHN * NT];
__device__ float g_pm[BHN * NSPLIT * NT];
__device__ float g_pl[BHN * NSPLIT * NT];
__device__ float g_po[BHN * NSPLIT * NT * DD];

// ---------------- packed f32x2 helpers ----------------
__device__ __forceinline__ unsigned long long pk2(float x, float y) {
    unsigned long long r;
    asm("mov.b64 %0, {%1, %2};" : "=l"(r) : "f"(x), "f"(y));
    return r;
}
__device__ __forceinline__ unsigned long long ffma2(unsigned long long a,
                                                    unsigned long long b,
                                                    unsigned long long c) {
    unsigned long long d;
    asm("fma.rn.f32x2 %0, %1, %2, %3;" : "=l"(d) : "l"(a), "l"(b), "l"(c));
    return d;
}
__device__ __forceinline__ unsigned long long fmul2(unsigned long long a,
                                                    unsigned long long b) {
    unsigned long long d;
    asm("mul.rn.f32x2 %0, %1, %2;" : "=l"(d) : "l"(a), "l"(b));
    return d;
}

// ---------------- detect index dtype (int64 vs int32) ----------------
__global__ void detect_idx_kernel(const long long* __restrict__ idx64) {
    int ok = 1;
    for (int i = threadIdx.x; i < 512; i += 32) {
        long long v = idx64[i];
        if (v < 0 || v >= LL) ok = 0;
    }
    unsigned m = __ballot_sync(0xffffffffu, ok);
    if (threadIdx.x == 0) g_is64 = (m == 0xffffffffu) ? 1 : 0;
}

// ---------------- sample_m (R3-proven): warp per (bh,l); 4 groups x 8 lanes ----------------
__global__ void sample_m_kernel(const float* __restrict__ Q,
                                const float* __restrict__ K,
                                const void*  __restrict__ idxbuf) {
    int wid  = (blockIdx.x * blockDim.x + threadIdx.x) >> 5;
    int lane = threadIdx.x & 31;
    int l  = wid % LL;
    int bh = wid / LL;
    int b = bh >> 3, h = bh & 7;
    int g  = lane >> 3;
    int li = lane & 7;

    int ia = 0, ib = 0;
    if (g_is64) {
        const long long* p = (const long long*)idxbuf + (long long)l * SK;
        ia = (int)p[lane];
        if (lane < SK - 32) ib = (int)p[32 + lane];
    } else {
        const int* p = (const int*)idxbuf + l * SK;
        ia = p[lane];
        if (lane < SK - 32) ib = p[32 + lane];
    }

    const float* qbase = Q + (((size_t)(b * LL + l) * HH + h) << 6) + (li << 3);
    const float4 qa = ((const float4*)qbase)[0];
    const float4 qb = ((const float4*)qbase)[1];

    const size_t kstride_h = ((size_t)h << 6) + ((size_t)li << 3);
    const float* Kb = K + ((size_t)b * LL * HH << 6);

    float mx = -3e38f, sm = 0.0f;
#pragma unroll
    for (int r = 0; r < 10; r++) {
        int s = 4 * r + g;
        int j = (s < 32) ? __shfl_sync(0xffffffffu, ia, s)
                         : __shfl_sync(0xffffffffu, ib, s - 32);
        const float4* kp = (const float4*)(Kb + (((size_t)j * HH) << 6) + kstride_h);
        float4 k0 = kp[0];
        float4 k1 = kp[1];
        float p = qa.x * k0.x;
        p = fmaf(qa.y, k0.y, p);
        p = fmaf(qa.z, k0.z, p);
        p = fmaf(qa.w, k0.w, p);
        p = fmaf(qb.x, k1.x, p);
        p = fmaf(qb.y, k1.y, p);
        p = fmaf(qb.z, k1.z, p);
        p = fmaf(qb.w, k1.w, p);
        p += __shfl_xor_sync(0xffffffffu, p, 1);
        p += __shfl_xor_sync(0xffffffffu, p, 2);
        p += __shfl_xor_sync(0xffffffffu, p, 4);
        mx = fmaxf(mx, p);
        sm += p;
    }
    mx = fmaxf(mx, __shfl_xor_sync(0xffffffffu, mx, 8));
    mx = fmaxf(mx, __shfl_xor_sync(0xffffffffu, mx, 16));
    sm += __shfl_xor_sync(0xffffffffu, sm, 8);
    sm += __shfl_xor_sync(0xffffffffu, sm, 16);
    if (lane == 0) g_M[bh * LL + l] = mx - sm * (1.0f / (float)LL);
}

// ---------------- topk v3: per-lane top-3 stack + REDUX rounds ----------------
// key = (ordval<<32)|(2047-idx): larger key = higher value, tie -> lower index.
__global__ void topk_kernel() {
    __shared__ float sM[LL];
    int bh = blockIdx.x, lane = threadIdx.x;
    for (int i = lane; i < LL; i += 32) sM[i] = g_M[bh * LL + i];
    __syncwarp();

    int base = lane << 6;
    unsigned long long s0 = 0ull, s1 = 0ull, s2 = 0ull;
#pragma unroll 4
    for (int i = 0; i < 64; i++) {
        float x = sM[base + i];
        unsigned uv = __float_as_uint(x);
        uv ^= (uv >> 31) ? 0xffffffffu : 0x80000000u;
        unsigned long long k = ((unsigned long long)uv << 32)
                             | (unsigned)(LL - 1 - (base + i));
        if (k > s0)      { s2 = s1; s1 = s0; s0 = k; }
        else if (k > s1) { s2 = s1; s1 = k; }
        else if (k > s2) { s2 = k; }
    }

    for (int it = 0; it < NT; it++) {
        unsigned ord0 = (unsigned)(s0 >> 32);
        unsigned m1 = __reduce_max_sync(0xffffffffu, ord0);
        unsigned lowp = (ord0 == m1) ? ((unsigned)s0 + 1u) : 0u;
        unsigned m2 = __reduce_max_sync(0xffffffffu, lowp);
        int wi = LL - (int)m2;
        if (lane == 0) g_top[bh * NT + it] = wi;
        if (lane == (wi >> 6)) {
            sM[wi] = -3e38f;
            s0 = s1; s1 = s2; s2 = 0ull;
            if (s0 == 0ull) {   // rare: segment popped 3+ times -> rescan
                for (int i = 0; i < 64; i++) {
                    float x = sM[base + i];
                    unsigned uv = __float_as_uint(x);
                    uv ^= (uv >> 31) ? 0xffffffffu : 0x80000000u;
                    unsigned long long k = ((unsigned long long)uv << 32)
                                         | (unsigned)(LL - 1 - (base + i));
                    if (k > s0)      { s2 = s1; s1 = s0; s0 = k; }
                    else if (k > s1) { s2 = s1; s1 = k; }
                    else if (k > s2) { s2 = k; }
                }
            }
        }
        __syncwarp();
    }
}

// ---------------- split-K attention (R4-proven): 63KB smem, f32x2 ----------------
__global__ void attn_kernel(const float* __restrict__ Q,
                            const float* __restrict__ K,
                            const float* __restrict__ V) {
    extern __shared__ float smem[];
    int bh = blockIdx.x / NSPLIT, split = blockIdx.x % NSPLIT;
    int b = bh >> 3, h = bh & 7;
    int t = threadIdx.x;

    float* Qs = smem;                  // 2560
    float* Kt = Qs + NT * DD;          // 8448
    float* Ss = Kt + 64 * 132;         // 5120

    for (int i = t; i < NT * DD; i += 256) {
        int u = i >> 6, d = i & 63;
        int ql = g_top[bh * NT + u];
        Qs[i] = Q[(((size_t)(b * LL + ql) * HH + h) << 6) + d];
    }
    int key0 = split * CHUNK;
    for (int i = t; i < CHUNK * DD; i += 256) {
        int j = i >> 6, d = i & 63;
        Kt[d * 132 + j] = K[(((size_t)(b * LL + key0 + j) * HH + h) << 6) + d];
    }
    __syncthreads();

    {
        int ublk = t >> 5;
        int jg   = t & 31;
        unsigned long long a01[5], a23[5];
#pragma unroll
        for (int k = 0; k < 5; k++) { a01[k] = 0ull; a23[k] = 0ull; }
        const ulonglong2* Kt2 = (const ulonglong2*)Kt;
#pragma unroll 8
        for (int d = 0; d < 64; d++) {
            ulonglong2 kv = Kt2[d * 33 + jg];
#pragma unroll
            for (int k = 0; k < 5; k++) {
                float qv = Qs[(ublk * 5 + k) * 64 + d];
                unsigned long long qq = pk2(qv, qv);
                a01[k] = ffma2(qq, kv.x, a01[k]);
                a23[k] = ffma2(qq, kv.y, a23[k]);
            }
        }
        unsigned long long sc = pk2(SCALE, SCALE);
#pragma unroll
        for (int k = 0; k < 5; k++) {
            int u = ublk * 5 + k;
            ulonglong2 sv;
            sv.x = fmul2(a01[k], sc);
            sv.y = fmul2(a23[k], sc);
            *(ulonglong2*)(Ss + u * CHUNK + (jg << 2)) = sv;
        }
    }
    __syncthreads();

    {
        int w = t >> 5, lane = t & 31;
        for (int r = w * 5; r < w * 5 + 5; r++) {
            float v0 = Ss[r * CHUNK + lane];
            float v1 = Ss[r * CHUNK + lane + 32];
            float v2 = Ss[r * CHUNK + lane + 64];
            float v3 = Ss[r * CHUNK + lane + 96];
            float m = fmaxf(fmaxf(v0, v1), fmaxf(v2, v3));
#pragma unroll
            for (int o = 16; o; o >>= 1) m = fmaxf(m, __shfl_xor_sync(0xffffffffu, m, o));
            float e0 = __expf(v0 - m), e1 = __expf(v1 - m);
            float e2 = __expf(v2 - m), e3 = __expf(v3 - m);
            Ss[r * CHUNK + lane]      = e0;
            Ss[r * CHUNK + lane + 32] = e1;
            Ss[r * CHUNK + lane + 64] = e2;
            Ss[r * CHUNK + lane + 96] = e3;
            float s = e0 + e1 + e2 + e3;
#pragma unroll
            for (int o = 16; o; o >>= 1) s += __shfl_xor_sync(0xffffffffu, s, o);
            if (lane == 0) {
                g_pm[(bh * NSPLIT + split) * NT + r] = m;
                g_pl[(bh * NSPLIT + split) * NT + r] = s;
            }
        }
    }
    __syncthreads();

    {
        int ublk = t >> 5;
        int d4   = t & 15;
        int jh   = (t >> 4) & 1;
        unsigned long long a01[5], a23[5];
#pragma unroll
        for (int k = 0; k < 5; k++) { a01[k] = 0ull; a23[k] = 0ull; }
        int j0 = jh * 64;
#pragma unroll 4
        for (int jj = 0; jj < 64; jj++) {
            int j = j0 + jj;
            ulonglong2 vv = *(const ulonglong2*)
                (V + (((size_t)(b * LL + key0 + j) * HH + h) << 6) + (d4 << 2));
#pragma unroll
            for (int k = 0; k < 5; k++) {
                float p = Ss[(ublk * 5 + k) * CHUNK + j];
                unsigned long long pp = pk2(p, p);
                a01[k] = ffma2(pp, vv.x, a01[k]);
                a23[k] = ffma2(pp, vv.y, a23[k]);
            }
        }
        float* Opart = Kt;
#pragma unroll
        for (int k = 0; k < 5; k++) {
            int u = ublk * 5 + k;
            ulonglong2 ov; ov.x = a01[k]; ov.y = a23[k];
            *(ulonglong2*)(Opart + (jh * NT + u) * 64 + (d4 << 2)) = ov;
        }
    }
    __syncthreads();

    for (int i = t; i < NT * DD; i += 256) {
        float v = Kt[i] + Kt[NT * DD + i];
        g_po[(size_t)(bh * NSPLIT + split) * NT * DD + i] = v;
    }
}

// ---------------- combine v2 (R4-proven): 256 blocks ----------------
__global__ void combine_kernel(float* __restrict__ out) {
    __shared__ float sw[5 * NSPLIT];
    __shared__ float sl[5];
    int bid = blockIdx.x;
    int bh = bid >> 3, uc = bid & 7;
    int b = bh >> 3, h = bh & 7;
    int t = threadIdx.x;

    if (t < 5) {
        int u = uc * 5 + t;
        float m = -3e38f;
#pragma unroll
        for (int s = 0; s < NSPLIT; s++)
            m = fmaxf(m, g_pm[(bh * NSPLIT + s) * NT + u]);
        float Ls = 0.f;
#pragma unroll
        for (int s = 0; s < NSPLIT; s++) {
            float w = __expf(g_pm[(bh * NSPLIT + s) * NT + u] - m);
            sw[t * NSPLIT + s] = w;
            Ls += g_pl[(bh * NSPLIT + s) * NT + u] * w;
        }
        sl[t] = Ls;
    }
    __syncthreads();
    for (int i = t; i < 5 * DD; i += 256) {
        int uu = i >> 6, d = i & 63;
        int u = uc * 5 + uu;
        float acc = 0.f;
#pragma unroll
        for (int s = 0; s < NSPLIT; s++)
            acc += sw[uu * NSPLIT + s] *
                   g_po[(size_t)(bh * NSPLIT + s) * NT * DD + u * DD + d];
        out[(((size_t)(b * NT + u) * HH + h) << 6) + d] = acc / sl[uu];
    }
}

// ---------------- launcher ----------------
extern "C" void kernel_launch(void* const* d_in, const int* in_sizes, int n_in,
                              void* d_out, int out_size) {
    const float* Q   = (const float*)d_in[0];
    const float* K   = (const float*)d_in[1];
    const float* V   = (const float*)d_in[2];
    const void*  idx = d_in[3];

    detect_idx_kernel<<<1, 32>>>((const long long*)idx);
    sample_m_kernel<<<(BHN * LL) / 8, 256>>>(Q, K, idx);
    topk_kernel<<<BHN, 32>>>();

    size_t smemD = (size_t)(NT * DD + 64 * 132 + NT * CHUNK) * sizeof(float); // 64512 B
    cudaFuncSetAttribute(attn_kernel, cudaFuncAttributeMaxDynamicSharedMemorySize, (int)smemD);
    attn_kernel<<<BHN * NSPLIT, 256, smemD>>>(Q, K, V);

    combine_kernel<<<BHN * 8, 256>>>((float*)d_out);
}

// round 6
// speedup vs baseline: 4.0563x; 1.0343x over previous
#include <cuda_runtime.h>
#include <cstddef>

#define BB 4
#define LL 2048
#define HH 8
#define DD 64
#define SK 40
#define NT 40
#define BHN 32
#define NSPLIT 16
#define CHUNK 128
#define SCALE 0.125f

// ---------------- scratch ----------------
__device__ int   g_is64;
__device__ float g_M[BHN * LL];
__device__ int   g_top[BHN * NT];
__device__ float g_pm[BHN * NSPLIT * NT];
__device__ float g_pl[BHN * NSPLIT * NT];
__device__ float g_po[BHN * NSPLIT * NT * DD];

// ---------------- detect index dtype (int64 vs int32) ----------------
__global__ void detect_idx_kernel(const long long* __restrict__ idx64) {
    int ok = 1;
    for (int i = threadIdx.x; i < 512; i += 32) {
        long long v = idx64[i];
        if (v < 0 || v >= LL) ok = 0;
    }
    unsigned m = __ballot_sync(0xffffffffu, ok);
    if (threadIdx.x == 0) g_is64 = (m == 0xffffffffu) ? 1 : 0;
}

// ---------------- sample_m (R3-proven): warp per (bh,l); 4 groups x 8 lanes ----------------
__global__ void sample_m_kernel(const float* __restrict__ Q,
                                const float* __restrict__ K,
                                const void*  __restrict__ idxbuf) {
    int wid  = (blockIdx.x * blockDim.x + threadIdx.x) >> 5;
    int lane = threadIdx.x & 31;
    int l  = wid % LL;
    int bh = wid / LL;
    int b = bh >> 3, h = bh & 7;
    int g  = lane >> 3;
    int li = lane & 7;

    int ia = 0, ib = 0;
    if (g_is64) {
        const long long* p = (const long long*)idxbuf + (long long)l * SK;
        ia = (int)p[lane];
        if (lane < SK - 32) ib = (int)p[32 + lane];
    } else {
        const int* p = (const int*)idxbuf + l * SK;
        ia = p[lane];
        if (lane < SK - 32) ib = p[32 + lane];
    }

    const float* qbase = Q + (((size_t)(b * LL + l) * HH + h) << 6) + (li << 3);
    const float4 qa = ((const float4*)qbase)[0];
    const float4 qb = ((const float4*)qbase)[1];

    const size_t kstride_h = ((size_t)h << 6) + ((size_t)li << 3);
    const float* Kb = K + ((size_t)b * LL * HH << 6);

    float mx = -3e38f, sm = 0.0f;
#pragma unroll
    for (int r = 0; r < 10; r++) {
        int s = 4 * r + g;
        int j = (s < 32) ? __shfl_sync(0xffffffffu, ia, s)
                         : __shfl_sync(0xffffffffu, ib, s - 32);
        const float4* kp = (const float4*)(Kb + (((size_t)j * HH) << 6) + kstride_h);
        float4 k0 = kp[0];
        float4 k1 = kp[1];
        float p = qa.x * k0.x;
        p = fmaf(qa.y, k0.y, p);
        p = fmaf(qa.z, k0.z, p);
        p = fmaf(qa.w, k0.w, p);
        p = fmaf(qb.x, k1.x, p);
        p = fmaf(qb.y, k1.y, p);
        p = fmaf(qb.z, k1.z, p);
        p = fmaf(qb.w, k1.w, p);
        p += __shfl_xor_sync(0xffffffffu, p, 1);
        p += __shfl_xor_sync(0xffffffffu, p, 2);
        p += __shfl_xor_sync(0xffffffffu, p, 4);
        mx = fmaxf(mx, p);
        sm += p;
    }
    mx = fmaxf(mx, __shfl_xor_sync(0xffffffffu, mx, 8));
    mx = fmaxf(mx, __shfl_xor_sync(0xffffffffu, mx, 16));
    sm += __shfl_xor_sync(0xffffffffu, sm, 8);
    sm += __shfl_xor_sync(0xffffffffu, sm, 16);
    if (lane == 0) g_M[bh * LL + l] = mx - sm * (1.0f / (float)LL);
}

// ---------------- topk v3 (R5-proven): per-lane top-3 stack + REDUX ----------------
__global__ void topk_kernel() {
    __shared__ float sM[LL];
    int bh = blockIdx.x, lane = threadIdx.x;
    for (int i = lane; i < LL; i += 32) sM[i] = g_M[bh * LL + i];
    __syncwarp();

    int base = lane << 6;
    unsigned long long s0 = 0ull, s1 = 0ull, s2 = 0ull;
#pragma unroll 4
    for (int i = 0; i < 64; i++) {
        float x = sM[base + i];
        unsigned uv = __float_as_uint(x);
        uv ^= (uv >> 31) ? 0xffffffffu : 0x80000000u;
        unsigned long long k = ((unsigned long long)uv << 32)
                             | (unsigned)(LL - 1 - (base + i));
        if (k > s0)      { s2 = s1; s1 = s0; s0 = k; }
        else if (k > s1) { s2 = s1; s1 = k; }
        else if (k > s2) { s2 = k; }
    }

    for (int it = 0; it < NT; it++) {
        unsigned ord0 = (unsigned)(s0 >> 32);
        unsigned m1 = __reduce_max_sync(0xffffffffu, ord0);
        unsigned lowp = (ord0 == m1) ? ((unsigned)s0 + 1u) : 0u;
        unsigned m2 = __reduce_max_sync(0xffffffffu, lowp);
        int wi = LL - (int)m2;
        if (lane == 0) g_top[bh * NT + it] = wi;
        if (lane == (wi >> 6)) {
            sM[wi] = -3e38f;
            s0 = s1; s1 = s2; s2 = 0ull;
            if (s0 == 0ull) {
                for (int i = 0; i < 64; i++) {
                    float x = sM[base + i];
                    unsigned uv = __float_as_uint(x);
                    uv ^= (uv >> 31) ? 0xffffffffu : 0x80000000u;
                    unsigned long long k = ((unsigned long long)uv << 32)
                                         | (unsigned)(LL - 1 - (base + i));
                    if (k > s0)      { s2 = s1; s1 = s0; s0 = k; }
                    else if (k > s1) { s2 = s1; s1 = k; }
                    else if (k > s2) { s2 = k; }
                }
            }
        }
        __syncwarp();
    }
}

// ---------------- split-K attention: R1 structure + paired-LDS inner loops ----------------
__global__ void attn_kernel(const float* __restrict__ Q,
                            const float* __restrict__ K,
                            const float* __restrict__ V) {
    extern __shared__ float smem[];
    int bh = blockIdx.x / NSPLIT, split = blockIdx.x % NSPLIT;
    int b = bh >> 3, h = bh & 7;
    int t = threadIdx.x;

    float* Qs = smem;                  // 2560
    float* Kt = Qs + NT * DD;          // 8448
    float* Vs = Kt + 64 * 132;         // 8192
    float* Ss = Vs + CHUNK * DD;       // 5120

    for (int i = t; i < NT * DD; i += 256) {
        int u = i >> 6, d = i & 63;
        int ql = g_top[bh * NT + u];
        Qs[i] = Q[(((size_t)(b * LL + ql) * HH + h) << 6) + d];
    }
    int key0 = split * CHUNK;
    for (int i = t; i < CHUNK * DD; i += 256) {
        int j = i >> 6, d = i & 63;
        size_t gbase = ((size_t)(b * LL + key0 + j) * HH + h) << 6;
        Kt[d * 132 + j] = K[gbase + d];
        Vs[i]           = V[gbase + d];
    }
    __syncthreads();

    // ---- phase 1: scores; d-pairs (float2 Q load), order-preserving ----
    {
        int ublk = t >> 5;
        int jg   = t & 31;
        float4 acc[5];
#pragma unroll
        for (int k = 0; k < 5; k++) acc[k] = make_float4(0.f, 0.f, 0.f, 0.f);
        const float4* Kt4 = (const float4*)Kt;
#pragma unroll 8
        for (int d = 0; d < 64; d += 2) {
            float4 kv0 = Kt4[d * 33 + jg];
            float4 kv1 = Kt4[(d + 1) * 33 + jg];
#pragma unroll
            for (int k = 0; k < 5; k++) {
                float2 qv = *(const float2*)(Qs + (ublk * 5 + k) * 64 + d);
                acc[k].x += qv.x * kv0.x;
                acc[k].y += qv.x * kv0.y;
                acc[k].z += qv.x * kv0.z;
                acc[k].w += qv.x * kv0.w;
                acc[k].x += qv.y * kv1.x;
                acc[k].y += qv.y * kv1.y;
                acc[k].z += qv.y * kv1.z;
                acc[k].w += qv.y * kv1.w;
            }
        }
#pragma unroll
        for (int k = 0; k < 5; k++) {
            int u = ublk * 5 + k;
            float4 sv = make_float4(acc[k].x * SCALE, acc[k].y * SCALE,
                                    acc[k].z * SCALE, acc[k].w * SCALE);
            *(float4*)(Ss + u * CHUNK + (jg << 2)) = sv;
        }
    }
    __syncthreads();

    // ---- phase 1.5: partial softmax ----
    {
        int w = t >> 5, lane = t & 31;
        for (int r = w * 5; r < w * 5 + 5; r++) {
            float v0 = Ss[r * CHUNK + lane];
            float v1 = Ss[r * CHUNK + lane + 32];
            float v2 = Ss[r * CHUNK + lane + 64];
            float v3 = Ss[r * CHUNK + lane + 96];
            float m = fmaxf(fmaxf(v0, v1), fmaxf(v2, v3));
#pragma unroll
            for (int o = 16; o; o >>= 1) m = fmaxf(m, __shfl_xor_sync(0xffffffffu, m, o));
            float e0 = __expf(v0 - m), e1 = __expf(v1 - m);
            float e2 = __expf(v2 - m), e3 = __expf(v3 - m);
            Ss[r * CHUNK + lane]      = e0;
            Ss[r * CHUNK + lane + 32] = e1;
            Ss[r * CHUNK + lane + 64] = e2;
            Ss[r * CHUNK + lane + 96] = e3;
            float s = e0 + e1 + e2 + e3;
#pragma unroll
            for (int o = 16; o; o >>= 1) s += __shfl_xor_sync(0xffffffffu, s, o);
            if (lane == 0) {
                g_pm[(bh * NSPLIT + split) * NT + r] = m;
                g_pl[(bh * NSPLIT + split) * NT + r] = s;
            }
        }
    }
    __syncthreads();

    // ---- phase 2: O_partial = P @ V; j-pairs (float2 P load), order-preserving ----
    {
        int ublk = t >> 5;
        int d4   = t & 15;
        int jh   = (t >> 4) & 1;
        float4 acc[5];
#pragma unroll
        for (int k = 0; k < 5; k++) acc[k] = make_float4(0.f, 0.f, 0.f, 0.f);
        const float4* Vs4 = (const float4*)Vs;
        int j0 = jh * 64;
#pragma unroll 4
        for (int jj = 0; jj < 64; jj += 2) {
            int j = j0 + jj;
            float4 vv0 = Vs4[j * 16 + d4];
            float4 vv1 = Vs4[(j + 1) * 16 + d4];
#pragma unroll
            for (int k = 0; k < 5; k++) {
                float2 p = *(const float2*)(Ss + (ublk * 5 + k) * CHUNK + j);
                acc[k].x += p.x * vv0.x;
                acc[k].y += p.x * vv0.y;
                acc[k].z += p.x * vv0.z;
                acc[k].w += p.x * vv0.w;
                acc[k].x += p.y * vv1.x;
                acc[k].y += p.y * vv1.y;
                acc[k].z += p.y * vv1.z;
                acc[k].w += p.y * vv1.w;
            }
        }
        float* Opart = Kt;
#pragma unroll
        for (int k = 0; k < 5; k++) {
            int u = ublk * 5 + k;
            *(float4*)(Opart + (jh * NT + u) * 64 + (d4 << 2)) = acc[k];
        }
    }
    __syncthreads();

    for (int i = t; i < NT * DD; i += 256) {
        float v = Kt[i] + Kt[NT * DD + i];
        g_po[(size_t)(bh * NSPLIT + split) * NT * DD + i] = v;
    }
}

// ---------------- combine v2 (R4-proven): 256 blocks ----------------
__global__ void combine_kernel(float* __restrict__ out) {
    __shared__ float sw[5 * NSPLIT];
    __shared__ float sl[5];
    int bid = blockIdx.x;
    int bh = bid >> 3, uc = bid & 7;
    int b = bh >> 3, h = bh & 7;
    int t = threadIdx.x;

    if (t < 5) {
        int u = uc * 5 + t;
        float m = -3e38f;
#pragma unroll
        for (int s = 0; s < NSPLIT; s++)
            m = fmaxf(m, g_pm[(bh * NSPLIT + s) * NT + u]);
        float Ls = 0.f;
#pragma unroll
        for (int s = 0; s < NSPLIT; s++) {
            float w = __expf(g_pm[(bh * NSPLIT + s) * NT + u] - m);
            sw[t * NSPLIT + s] = w;
            Ls += g_pl[(bh * NSPLIT + s) * NT + u] * w;
        }
        sl[t] = Ls;
    }
    __syncthreads();
    for (int i = t; i < 5 * DD; i += 256) {
        int uu = i >> 6, d = i & 63;
        int u = uc * 5 + uu;
        float acc = 0.f;
#pragma unroll
        for (int s = 0; s < NSPLIT; s++)
            acc += sw[uu * NSPLIT + s] *
                   g_po[(size_t)(bh * NSPLIT + s) * NT * DD + u * DD + d];
        out[(((size_t)(b * NT + u) * HH + h) << 6) + d] = acc / sl[uu];
    }
}

// ---------------- launcher ----------------
extern "C" void kernel_launch(void* const* d_in, const int* in_sizes, int n_in,
                              void* d_out, int out_size) {
    const float* Q   = (const float*)d_in[0];
    const float* K   = (const float*)d_in[1];
    const float* V   = (const float*)d_in[2];
    const void*  idx = d_in[3];

    detect_idx_kernel<<<1, 32>>>((const long long*)idx);
    sample_m_kernel<<<(BHN * LL) / 8, 256>>>(Q, K, idx);
    topk_kernel<<<BHN, 32>>>();

    size_t smemD = (size_t)(NT * DD + 64 * 132 + CHUNK * DD + NT * CHUNK) * sizeof(float); // 97280
    cudaFuncSetAttribute(attn_kernel, cudaFuncAttributeMaxDynamicSharedMemorySize, (int)smemD);
    attn_kernel<<<BHN * NSPLIT, 256, smemD>>>(Q, K, V);

    combine_kernel<<<BHN * 8, 256>>>((float*)d_out);
}